// round 4
// baseline (speedup 1.0000x reference)
#include <cuda_runtime.h>

#define B_  2048
#define NL  64
#define NN  16
#define NO  2048
#define ZD  80          // NL + NN
#define MT  16          // rows per GEMM tile
#define K5T 512         // threads in GEMM kernel
#define MAX_TILES 160   // >= max possible tiles = 128 + 15 = 143

// ---- scratch (device globals; no allocation allowed) ----
__device__ float g_Wg[NN * NL * NO];   // 8 MB combined weights
__device__ int   g_nid[B_];
__device__ int   g_rows[B_];
__device__ int   g_counts[NN];
__device__ int   g_cursor[NN];
__device__ int   g_tile_group[MAX_TILES];
__device__ int   g_tile_rstart[MAX_TILES];
__device__ int   g_tile_rend[MAX_TILES];
__device__ int   g_num_tiles;

// ---- packed fp32x2 helpers (Blackwell FFMA2 path) ----
__device__ __forceinline__ unsigned long long pk2(float a, float b) {
    unsigned long long r;
    asm("mov.b64 %0, {%1, %2};" : "=l"(r) : "f"(a), "f"(b));
    return r;
}
__device__ __forceinline__ void unpk2(unsigned long long u, float& a, float& b) {
    asm("mov.b64 {%0, %1}, %2;" : "=f"(a), "=f"(b) : "l"(u));
}
#define FMA2(acc, a, b) \
    asm("fma.rn.f32x2 %0, %1, %2, %3;" : "=l"(acc) : "l"(a), "l"(b), "l"(acc))

// ---- K0: zero group counts (graph replays: must re-zero every launch) ----
__global__ void k0_zero() {
    int t = threadIdx.x;
    if (t < NN) g_counts[t] = 0;
}

// ---- K1: per-row argmax over nuisance one-hot + histogram ----
__global__ void k1_nid(const float* __restrict__ z) {
    int b = blockIdx.x * blockDim.x + threadIdx.x;
    if (b >= B_) return;
    const float* p = z + b * ZD + NL;
    float best = p[0];
    int   bi   = 0;
    #pragma unroll
    for (int j = 1; j < NN; j++) {
        float v = p[j];
        if (v > best) { best = v; bi = j; }   // strict '>' == jnp.argmax first-max
    }
    g_nid[b] = bi;
    atomicAdd(&g_counts[bi], 1);
}

// ---- K2: serial prefix sum + tile map (16 groups, trivial) ----
__global__ void k2_plan() {
    if (threadIdx.x != 0) return;
    int off = 0, t = 0;
    for (int g = 0; g < NN; g++) {
        int c = g_counts[g];
        g_cursor[g] = off;
        int nt = (c + MT - 1) / MT;
        for (int i = 0; i < nt; i++) {
            g_tile_group[t]  = g;
            g_tile_rstart[t] = off + i * MT;
            int e  = off + (i + 1) * MT;
            int ge = off + c;
            g_tile_rend[t] = e < ge ? e : ge;
            t++;
        }
        off += c;
    }
    g_num_tiles = t;
}

// ---- K3: scatter row ids into group-sorted order ----
__global__ void k3_scatter() {
    int b = blockIdx.x * blockDim.x + threadIdx.x;
    if (b >= B_) return;
    int pos = atomicAdd(&g_cursor[g_nid[b]], 1);
    g_rows[pos] = b;
}

// ---- K4: Wg[g] = amat_w + amat_site[g]  (float4, 524288 elems) ----
__global__ void k4_wg(const float* __restrict__ w, const float* __restrict__ site) {
    int idx = blockIdx.x * blockDim.x + threadIdx.x;   // float4 index, < 16*64*2048/4
    const float4* w4 = (const float4*)w;
    const float4* s4 = (const float4*)site;
    float4*       o4 = (float4*)g_Wg;
    float4 a = w4[idx & (NL * NO / 4 - 1)];
    float4 b = s4[idx];
    float4 r;
    r.x = a.x + b.x; r.y = a.y + b.y; r.z = a.z + b.z; r.w = a.w + b.w;
    o4[idx] = r;
}

// ---- K5: fused [16-row x 2048-col] GEMM (K=64, FFMA2) + softmax + scale ----
__global__ __launch_bounds__(K5T, 1)
void k5_gemm_softmax(const float* __restrict__ z,
                     const float* __restrict__ sf,
                     const float* __restrict__ offsets,
                     float* __restrict__ out) {
    int t = blockIdx.x;
    if (t >= g_num_tiles) return;           // uniform per block, before any barrier
    const int tid = threadIdx.x;
    const int g   = g_tile_group[t];
    const int rs  = g_tile_rstart[t];
    const int re  = g_tile_rend[t];
    const int nrows = re - rs;

    __shared__ unsigned long long s_zz[MT][NL];  // pre-broadcast {z,z} pairs, 8 KB
    __shared__ int   s_row[MT];
    __shared__ float s_red[MT][16];
    __shared__ float s_rowmax[MT];
    __shared__ float s_scale[MT];

    if (tid < MT) s_row[tid] = (tid < nrows) ? g_rows[rs + tid] : -1;
    __syncthreads();

    for (int i = tid; i < MT * NL; i += K5T) {
        int m = i >> 6, k = i & 63;
        int r = s_row[m];
        float v = (r >= 0) ? z[r * ZD + k] : 0.f;
        s_zz[m][k] = pk2(v, v);
    }
    __syncthreads();

    // thread owns contiguous cols [4*tid, 4*tid+3] as two packed f32x2 accums
    const float4* W4 = (const float4*)(g_Wg) + (size_t)g * (NL * NO / 4);
    unsigned long long acc[MT][2];
    #pragma unroll
    for (int m = 0; m < MT; m++) { acc[m][0] = 0ull; acc[m][1] = 0ull; }

    #pragma unroll 4
    for (int k = 0; k < NL; k++) {
        float4 w = W4[k * (NO / 4) + tid];          // LDG.128, perfectly coalesced
        unsigned long long w01 = pk2(w.x, w.y);
        unsigned long long w23 = pk2(w.z, w.w);
        #pragma unroll
        for (int m = 0; m < MT; m++) {
            unsigned long long zz = s_zz[m][k];     // LDS.64 broadcast
            FMA2(acc[m][0], zz, w01);
            FMA2(acc[m][1], zz, w23);
        }
    }

    // epilogue: + offsets, softmax over 2048 cols (distributed), * size_factor
    float4 of = ((const float4*)offsets)[g * (NO / 4) + tid];
    float v[MT][4];
    #pragma unroll
    for (int m = 0; m < MT; m++) {
        float a0, a1, a2, a3;
        unpk2(acc[m][0], a0, a1);
        unpk2(acc[m][1], a2, a3);
        v[m][0] = a0 + of.x; v[m][1] = a1 + of.y;
        v[m][2] = a2 + of.z; v[m][3] = a3 + of.w;
    }

    const int lane = tid & 31, wrp = tid >> 5;
    #pragma unroll
    for (int m = 0; m < MT; m++) {
        float lm = fmaxf(fmaxf(v[m][0], v[m][1]), fmaxf(v[m][2], v[m][3]));
        #pragma unroll
        for (int s = 16; s; s >>= 1) lm = fmaxf(lm, __shfl_xor_sync(0xffffffffu, lm, s));
        if (lane == 0) s_red[m][wrp] = lm;
    }
    __syncthreads();
    if (tid < MT) {
        float rm = s_red[tid][0];
        #pragma unroll
        for (int w = 1; w < 16; w++) rm = fmaxf(rm, s_red[tid][w]);
        s_rowmax[tid] = rm;
    }
    __syncthreads();

    #pragma unroll
    for (int m = 0; m < MT; m++) {
        float rm = s_rowmax[m];
        v[m][0] = __expf(v[m][0] - rm);
        v[m][1] = __expf(v[m][1] - rm);
        v[m][2] = __expf(v[m][2] - rm);
        v[m][3] = __expf(v[m][3] - rm);
        float ls = (v[m][0] + v[m][1]) + (v[m][2] + v[m][3]);
        #pragma unroll
        for (int s = 16; s; s >>= 1) ls += __shfl_xor_sync(0xffffffffu, ls, s);
        if (lane == 0) s_red[m][wrp] = ls;
    }
    __syncthreads();
    if (tid < MT) {
        float s = 0.f;
        #pragma unroll
        for (int w = 0; w < 16; w++) s += s_red[tid][w];
        int r = s_row[tid];
        s_scale[tid] = (r >= 0) ? sf[r] / s : 0.f;   // size_factor shape (B,1)
    }
    __syncthreads();

    #pragma unroll
    for (int m = 0; m < MT; m++) {
        int r = s_row[m];
        if (r < 0) continue;
        float sc = s_scale[m];
        float4 o;
        o.x = v[m][0] * sc; o.y = v[m][1] * sc;
        o.z = v[m][2] * sc; o.w = v[m][3] * sc;
        *(float4*)(out + (size_t)r * NO + tid * 4) = o;   // STG.128 coalesced
    }
}

// ---- K6: theta = exp(px_r), appended after mu ----
__global__ void k6_theta(const float* __restrict__ px_r, float* __restrict__ out) {
    int i = blockIdx.x * blockDim.x + threadIdx.x;
    if (i < NO) out[(size_t)B_ * NO + i] = expf(px_r[i]);
}

extern "C" void kernel_launch(void* const* d_in, const int* in_sizes, int n_in,
                              void* d_out, int out_size) {
    const float* z         = (const float*)d_in[0];
    const float* sf        = (const float*)d_in[1];
    const float* amat_w    = (const float*)d_in[2];
    const float* amat_site = (const float*)d_in[3];
    const float* offsets   = (const float*)d_in[4];
    const float* px_r      = (const float*)d_in[5];
    float* out = (float*)d_out;

    k0_zero<<<1, 32>>>();
    k1_nid<<<B_ / 256, 256>>>(z);
    k2_plan<<<1, 32>>>();
    k3_scatter<<<B_ / 256, 256>>>();
    k4_wg<<<(NN * NL * NO / 4) / 512, 512>>>(amat_w, amat_site);
    k5_gemm_softmax<<<MAX_TILES, K5T>>>(z, sf, offsets, out);
    k6_theta<<<(NO + 255) / 256, 256>>>(px_r, out);
}